// round 9
// baseline (speedup 1.0000x reference)
#include <cuda_runtime.h>

// ESN recurrence on GB300 — single-hop tagged-word exchange.
//
// MEMORY-MODEL LAW (established R3/R4/R6/R7/R8):
//   Publish: st.release.gpu.u64 {tag<<32|f32bits}  (strong, tear-free 8B).
//   Poll:    ld.relaxed.gpu.u64 same address        (strong => defined value;
//            relaxed => no acquire serialization). Weak .cg polls racing a
//            strong store return UNDEFINED values on sm_103a. Acquire chains
//            serialize (R4: 165ms). Relaxed is the only correct+fast choice.
//
// Grid: 32 CTAs x 1024 threads; thread t polls exactly ONE contiguous word
// (warp-coalesced 256B/line) => poll traffic 256KB/iter chip-wide (16x less
// than the 128-CTA layout), keeping LTS clear for the critical publishes.

#define H        1024
#define T        50000
#define WASHOUT  200
#define NOUT     (T - WASHOUT)   // 49800
#define B        32              // CTAs (co-resident trivially)
#define R        (H / B)         // 32 rows per CTA
#define THREADS  1024            // 32 warps, 1 warp per row
#define NPART    1024            // per-row partials (= H)

// Tagged state grouped by producer CTA: one 256B line per (buffer, producer).
__device__ __align__(128) unsigned long long g_xt[2][B][R];   // [2][32][32]
__device__ float    g_coef[H];                    // coef[mask[h]] = w_out[h]
__device__ unsigned g_epoch;                      // bumped per replay
__device__ float    g_part[(size_t)NPART * NOUT]; // per-row readout partials

static __device__ __forceinline__ unsigned long long pack_tv(unsigned tag, float v) {
    return ((unsigned long long)tag << 32) | (unsigned long long)__float_as_uint(v);
}
static __device__ __forceinline__ unsigned long long ld_rlx_u64(const unsigned long long* p) {
    unsigned long long v;
    asm volatile("ld.relaxed.gpu.global.u64 %0, [%1];" : "=l"(v) : "l"(p) : "memory");
    return v;
}
static __device__ __forceinline__ void st_rel_u64(unsigned long long* p, unsigned long long v) {
    asm volatile("st.release.gpu.global.u64 [%0], %1;" :: "l"(p), "l"(v) : "memory");
}

// ---------------------------------------------------------------------------
// Prologue: bump epoch, publish x0 = 0 (tag = base), build coef scatter.
// Mask dtype probed in parallel (int64 has >=512 zero odd int32 slots).
// ---------------------------------------------------------------------------
__global__ void esn_prologue(const float* __restrict__ w_out,
                             const void* __restrict__ mask_raw) {
    const int* m32 = (const int*)mask_raw;
    const int t = threadIdx.x;                    // 0..1023

    int is64 = __syncthreads_count(((t & 1) != 0) && (m32[t] == 0)) >= 256;
    if (t == 0) g_epoch = g_epoch + 1u;
    __syncthreads();
    const unsigned base = g_epoch * (unsigned)(T + 2);

    int idx;
    if (is64) idx = (int)((const long long*)mask_raw)[t];
    else      idx = m32[t];
    g_coef[idx & 1023] = w_out[t];
    g_xt[0][t >> 5][t & 31] = pack_tv(base, 0.0f);  // x_0 = 0, tag = base
}

// ---------------------------------------------------------------------------
// Main persistent kernel: 32 CTAs x 1024 threads. Warp w owns row cta*32+w
// (1024 weights in 32 regs/lane). Per step:
//   thread t spin-polls ONE tagged word with ld.relaxed.gpu,
//   stages value to s_x[t], bar, reg-weight dot, shfl reduce, tanh,
//   lane0 release-publishes one tagged word, bar.
// Overwrite safety: a CTA publishes x_{k+1} only after all its threads staged
// x_k; x_k is complete only after every CTA consumed x_{k-1} => the buffer
// being overwritten has no remaining readers (2-step-lead induction).
// ---------------------------------------------------------------------------
__global__ void __launch_bounds__(THREADS, 1)
esn_main(const float* __restrict__ u,
         const float* __restrict__ w_in,
         const float* __restrict__ w_res) {
    __shared__ float s_x[H];                      // 4 KB staging

    const int tid  = threadIdx.x;
    const int warp = tid >> 5;
    const int lane = tid & 31;
    const int cta  = blockIdx.x;
    const int row  = cta * R + warp;

    // Weights into registers: lane l holds cols 4l+128j, j=0..7 (32 floats)
    float4 wreg[8];
    {
        const float4* wr = reinterpret_cast<const float4*>(w_res + (size_t)row * H);
        #pragma unroll
        for (int j = 0; j < 8; ++j)
            wreg[j] = __ldg(wr + lane + 32 * j);
    }
    const float my_win  = w_in[row];
    const float my_coef = g_coef[row];
    const unsigned base = g_epoch * (unsigned)(T + 2);
    float* part_row = &g_part[(size_t)row * NOUT];

    // thread t consumes word t: producer CTA t>>5, word t&31 (contiguous)
    const unsigned long long* gx[2] = { &g_xt[0][0][0] + tid, &g_xt[1][0][0] + tid };
    unsigned long long* mypub[2] = { &g_xt[0][cta][warp], &g_xt[1][cta][warp] };

    for (int k = 0; k < T; ++k) {
        const float uk = __ldg(u + k);            // issues early, used at tanh
        const unsigned want = base + (unsigned)k;
        const int buf = k & 1;

        // ---- spin on ONE strong-relaxed 8B word (matches store size) ------
        unsigned long long v;
        do { v = ld_rlx_u64(gx[buf]); } while ((unsigned)(v >> 32) != want);
        s_x[tid] = __uint_as_float((unsigned)v);
        __syncthreads();                          // all 1024 values staged

        // ---- register-weight dot product (4 accumulators) ------------------
        const float4* xr = reinterpret_cast<const float4*>(s_x);
        float a0 = 0.f, a1 = 0.f, a2 = 0.f, a3 = 0.f;
        #pragma unroll
        for (int j = 0; j < 8; j += 4) {
            float4 x0 = xr[lane + 32 * (j + 0)];
            float4 x1 = xr[lane + 32 * (j + 1)];
            float4 x2 = xr[lane + 32 * (j + 2)];
            float4 x3 = xr[lane + 32 * (j + 3)];
            a0 = fmaf(wreg[j+0].x, x0.x, a0); a0 = fmaf(wreg[j+0].y, x0.y, a0);
            a0 = fmaf(wreg[j+0].z, x0.z, a0); a0 = fmaf(wreg[j+0].w, x0.w, a0);
            a1 = fmaf(wreg[j+1].x, x1.x, a1); a1 = fmaf(wreg[j+1].y, x1.y, a1);
            a1 = fmaf(wreg[j+1].z, x1.z, a1); a1 = fmaf(wreg[j+1].w, x1.w, a1);
            a2 = fmaf(wreg[j+2].x, x2.x, a2); a2 = fmaf(wreg[j+2].y, x2.y, a2);
            a2 = fmaf(wreg[j+2].z, x2.z, a2); a2 = fmaf(wreg[j+2].w, x2.w, a2);
            a3 = fmaf(wreg[j+3].x, x3.x, a3); a3 = fmaf(wreg[j+3].y, x3.y, a3);
            a3 = fmaf(wreg[j+3].z, x3.z, a3); a3 = fmaf(wreg[j+3].w, x3.w, a3);
        }
        float acc = (a0 + a1) + (a2 + a3);
        #pragma unroll
        for (int off = 16; off > 0; off >>= 1)
            acc += __shfl_xor_sync(0xffffffffu, acc, off);

        if (lane == 0) {
            const float val = tanhf(fmaf(my_win, uk, acc));
            // single-hop publish: tag + value atomic in one strong 8B store
            st_rel_u64(mypub[buf ^ 1], pack_tv(want + 1u, val));
            if (k >= WASHOUT)
                part_row[k - WASHOUT] = val * my_coef;
        }
        __syncthreads();                          // protect s_x reuse next step
    }
}

// ---------------------------------------------------------------------------
// Finalize: deterministic fixed-order reduction of 1024 per-row partials.
// ---------------------------------------------------------------------------
__global__ void esn_finalize(float* __restrict__ out) {
    int t = blockIdx.x * blockDim.x + threadIdx.x;
    if (t < NOUT) {
        float s = 0.0f;
        #pragma unroll 8
        for (int r = 0; r < NPART; ++r)
            s += g_part[(size_t)r * NOUT + t];    // coalesced across threads
        out[t] = s;
    }
}

// ---------------------------------------------------------------------------
// Inputs (metadata order): u[50000] f32, w_in[1024] f32, w_res[1024*1024] f32,
// w_out[1024] f32, w_out_mask[1024] int (32/64 probed). Output: 49800 f32.
// ---------------------------------------------------------------------------
extern "C" void kernel_launch(void* const* d_in, const int* in_sizes, int n_in,
                              void* d_out, int out_size) {
    const float* u     = (const float*)d_in[0];
    const float* w_in  = (const float*)d_in[1];
    const float* w_res = (const float*)d_in[2];
    const float* w_out = (const float*)d_in[3];
    const void*  mask  = d_in[4];
    float*       out   = (float*)d_out;

    esn_prologue<<<1, 1024>>>(w_out, mask);
    esn_main<<<B, THREADS>>>(u, w_in, w_res);
    esn_finalize<<<(NOUT + 255) / 256, 256>>>(out);
}

// round 10
// speedup vs baseline: 1.1223x; 1.1223x over previous
#include <cuda_runtime.h>

// ESN recurrence on GB300 — single-hop tagged-word exchange (settled protocol):
//   publish: st.relaxed.gpu.u64 {tag<<32|f32bits}  (strong 8B, tear-free; tag
//            and value travel atomically so NO ordering semantics are needed)
//   poll:    ld.relaxed.gpu.u64 (strong => defined under race; relaxed => the
//            4 polls of one thread pipeline in ONE L2 round trip)
// Weak .cg polls are UNDEFINED under race (R3/R7/R8 failures); acquire chains
// serialize (R4); R6's anchor+validate cost 2 serial RTs -> fixed here.
//
// Grid 128 CTAs x 256 thr (8 rows/CTA): minimizes per-SM SMEM traffic
// (32KB/step vs 128KB at 32 rows/CTA -- R9's regression).

#define H        1024
#define T        50000
#define WASHOUT  200
#define NOUT     (T - WASHOUT)   // 49800
#define B        128             // CTAs (<=148 SMs -> co-resident, spin-safe)
#define R        (H / B)         // 8 rows per CTA
#define THREADS  256             // 8 warps, 1 warp per row
#define NPART    1024

// Tagged state grouped by producer CTA: one 128B line per (buffer, producer).
__device__ __align__(128) unsigned long long g_xt[2][B][16];  // [0..7] used
__device__ float    g_coef[H];
__device__ unsigned g_epoch;
__device__ float    g_part[(size_t)NPART * NOUT];

static __device__ __forceinline__ unsigned long long pack_tv(unsigned tag, float v) {
    return ((unsigned long long)tag << 32) | (unsigned long long)__float_as_uint(v);
}
static __device__ __forceinline__ unsigned long long ld_rlx_u64(const unsigned long long* p) {
    unsigned long long v;
    asm volatile("ld.relaxed.gpu.global.u64 %0, [%1];" : "=l"(v) : "l"(p) : "memory");
    return v;
}
static __device__ __forceinline__ void st_rlx_u64(unsigned long long* p, unsigned long long v) {
    asm volatile("st.relaxed.gpu.global.u64 [%0], %1;" :: "l"(p), "l"(v) : "memory");
}
// fast tanh: (e^{2x}-1)/(e^{2x}+1), MUFU.EX2+MUFU.RCP (~40cyc vs ~120 tanhf).
// err ~1e-6/step; recurrence gain <= 1/(1-rho)=10 => ~1e-5 total (gate 1e-3).
static __device__ __forceinline__ float fast_tanh(float x) {
    x = fminf(fmaxf(x, -20.0f), 20.0f);           // avoid inf/inf
    float t = __expf(2.0f * x);
    return __fdividef(t - 1.0f, t + 1.0f);
}

// ---------------------------------------------------------------------------
// Prologue: bump epoch, publish x0 = 0 (tag = base), build coef scatter.
// Mask dtype probed in parallel (int64 has >=512 zero odd int32 slots).
// ---------------------------------------------------------------------------
__global__ void esn_prologue(const float* __restrict__ w_out,
                             const void* __restrict__ mask_raw) {
    const int* m32 = (const int*)mask_raw;
    const int t = threadIdx.x;                    // 0..1023

    int is64 = __syncthreads_count(((t & 1) != 0) && (m32[t] == 0)) >= 256;
    if (t == 0) g_epoch = g_epoch + 1u;
    __syncthreads();
    const unsigned base = g_epoch * (unsigned)(T + 2);

    int idx;
    if (is64) idx = (int)((const long long*)mask_raw)[t];
    else      idx = m32[t];
    g_coef[idx & 1023] = w_out[t];
    g_xt[0][t >> 3][t & 7] = pack_tv(base, 0.0f); // x_0 = 0, tag = base
}

// ---------------------------------------------------------------------------
// Main persistent kernel. Warp w of CTA c owns row c*8+w (weights in regs).
// Thread t consumes words [w0..w0+3] of producer p = t/2:
//   one poll loop of 4 parallel relaxed loads (each word self-validates),
//   stage float4 into double-buffered s_x, bar, reg-weight dot, shfl reduce,
//   fast-tanh, lane0 publishes one tagged word. No trailing bar: the staging
//   bar of step k+1 proves all dots of step k done before buffer reuse at k+2.
// ---------------------------------------------------------------------------
__global__ void __launch_bounds__(THREADS, 1)
esn_main(const float* __restrict__ u,
         const float* __restrict__ w_in,
         const float* __restrict__ w_res) {
    __shared__ float s_x[2][H];                   // 8 KB, double-buffered

    const int tid  = threadIdx.x;
    const int warp = tid >> 5;
    const int lane = tid & 31;
    const int cta  = blockIdx.x;
    const int row  = cta * R + warp;
    const int p    = tid >> 1;                    // producer CTA of my float4
    const int w0   = (tid & 1) * 4;               // word offset within its line

    // Weights into registers: lane l holds cols 4l+128j, j=0..7 (32 floats)
    float4 wreg[8];
    {
        const float4* wr = reinterpret_cast<const float4*>(w_res + (size_t)row * H);
        #pragma unroll
        for (int j = 0; j < 8; ++j)
            wreg[j] = __ldg(wr + lane + 32 * j);
    }
    const float my_win  = w_in[row];
    const float my_coef = g_coef[row];
    const unsigned base = g_epoch * (unsigned)(T + 2);
    float* part_row = &g_part[(size_t)row * NOUT];

    const unsigned long long* gx[2] = { &g_xt[0][p][w0], &g_xt[1][p][w0] };
    unsigned long long* mypub[2] = { &g_xt[0][cta][warp], &g_xt[1][cta][warp] };

    for (int k = 0; k < T; ++k) {
        const float uk = __ldg(u + k);            // issues early, used at tanh
        const unsigned want = base + (unsigned)k;
        const int buf = k & 1;
        const unsigned long long* g = gx[buf];

        // ---- ONE poll round: 4 parallel strong-relaxed scalar 8B loads -----
        unsigned long long v0, v1, v2, v3;
        for (;;) {
            v0 = ld_rlx_u64(g + 0);
            v1 = ld_rlx_u64(g + 1);
            v2 = ld_rlx_u64(g + 2);
            v3 = ld_rlx_u64(g + 3);
            if ((unsigned)(v0 >> 32) == want && (unsigned)(v1 >> 32) == want &&
                (unsigned)(v2 >> 32) == want && (unsigned)(v3 >> 32) == want)
                break;
        }

        float4 xv;
        xv.x = __uint_as_float((unsigned)v0);
        xv.y = __uint_as_float((unsigned)v1);
        xv.z = __uint_as_float((unsigned)v2);
        xv.w = __uint_as_float((unsigned)v3);
        reinterpret_cast<float4*>(s_x[buf])[tid] = xv;
        __syncthreads();                          // all 1024 values staged

        // ---- register-weight dot product (4 accumulators) ------------------
        const float4* xr = reinterpret_cast<const float4*>(s_x[buf]);
        float a0 = 0.f, a1 = 0.f, a2 = 0.f, a3 = 0.f;
        #pragma unroll
        for (int j = 0; j < 8; j += 4) {
            float4 x0 = xr[lane + 32 * (j + 0)];
            float4 x1 = xr[lane + 32 * (j + 1)];
            float4 x2 = xr[lane + 32 * (j + 2)];
            float4 x3 = xr[lane + 32 * (j + 3)];
            a0 = fmaf(wreg[j+0].x, x0.x, a0); a0 = fmaf(wreg[j+0].y, x0.y, a0);
            a0 = fmaf(wreg[j+0].z, x0.z, a0); a0 = fmaf(wreg[j+0].w, x0.w, a0);
            a1 = fmaf(wreg[j+1].x, x1.x, a1); a1 = fmaf(wreg[j+1].y, x1.y, a1);
            a1 = fmaf(wreg[j+1].z, x1.z, a1); a1 = fmaf(wreg[j+1].w, x1.w, a1);
            a2 = fmaf(wreg[j+2].x, x2.x, a2); a2 = fmaf(wreg[j+2].y, x2.y, a2);
            a2 = fmaf(wreg[j+2].z, x2.z, a2); a2 = fmaf(wreg[j+2].w, x2.w, a2);
            a3 = fmaf(wreg[j+3].x, x3.x, a3); a3 = fmaf(wreg[j+3].y, x3.y, a3);
            a3 = fmaf(wreg[j+3].z, x3.z, a3); a3 = fmaf(wreg[j+3].w, x3.w, a3);
        }
        float acc = (a0 + a1) + (a2 + a3);
        #pragma unroll
        for (int off = 16; off > 0; off >>= 1)
            acc += __shfl_xor_sync(0xffffffffu, acc, off);

        if (lane == 0) {
            const float val = fast_tanh(fmaf(my_win, uk, acc));
            st_rlx_u64(mypub[buf ^ 1], pack_tv(want + 1u, val));  // publish
            if (k >= WASHOUT)
                part_row[k - WASHOUT] = val * my_coef;
        }
        // no trailing bar: s_x[buf] is rewritten only at step k+2, which is
        // gated by the staging bar of step k+1 (all dots of step k done).
    }
}

// ---------------------------------------------------------------------------
// Finalize: deterministic fixed-order reduction of 1024 per-row partials.
// ---------------------------------------------------------------------------
__global__ void esn_finalize(float* __restrict__ out) {
    int t = blockIdx.x * blockDim.x + threadIdx.x;
    if (t < NOUT) {
        float s = 0.0f;
        #pragma unroll 8
        for (int r = 0; r < NPART; ++r)
            s += g_part[(size_t)r * NOUT + t];    // coalesced across threads
        out[t] = s;
    }
}

// ---------------------------------------------------------------------------
// Inputs (metadata order): u[50000] f32, w_in[1024] f32, w_res[1024*1024] f32,
// w_out[1024] f32, w_out_mask[1024] int (32/64 probed). Output: 49800 f32.
// ---------------------------------------------------------------------------
extern "C" void kernel_launch(void* const* d_in, const int* in_sizes, int n_in,
                              void* d_out, int out_size) {
    const float* u     = (const float*)d_in[0];
    const float* w_in  = (const float*)d_in[1];
    const float* w_res = (const float*)d_in[2];
    const float* w_out = (const float*)d_in[3];
    const void*  mask  = d_in[4];
    float*       out   = (float*)d_out;

    esn_prologue<<<1, 1024>>>(w_out, mask);
    esn_main<<<B, THREADS>>>(u, w_in, w_res);
    esn_finalize<<<(NOUT + 255) / 256, 256>>>(out);
}